// round 7
// baseline (speedup 1.0000x reference)
#include <cuda_runtime.h>
#include <cuda_fp16.h>
#include <cstdint>

#define DT_F (1.0f/64.0f)
#define NSTEPS 64
#define NK 32
#define RTOT 16384
#define RAYS_PER_BLOCK 32
#define NTHREADS 1024
#define NBLOCKS (RTOT / RAYS_PER_BLOCK)         // 512
#define VOX_PER_PRIM 4096
// dynamic smem: 2 x 4096 uint2 (fp16x4 voxels) + 32*12 floats affine
#define SMEM_BYTES (2 * VOX_PER_PRIM * 8 + NK * 12 * 4)

// fp16-packed template: [k][z][y][x] -> uint2 (r,g | b,a as half2)
__device__ uint2 g_tplh[NK * VOX_PER_PRIM];

__global__ void convert_tpl_kernel(const float* __restrict__ tpl)
{
    const int idx = blockIdx.x * blockDim.x + threadIdx.x;   // 0 .. 131071
    const int k = idx >> 12;
    const int v = idx & 4095;
    const float* tk = tpl + (size_t)k * 4 * VOX_PER_PRIM;
    const float r = tk[v];
    const float g = tk[v + 4096];
    const float b = tk[v + 8192];
    const float a = tk[v + 12288];
    const half2 h0 = __floats2half2_rn(r, g);
    const half2 h1 = __floats2half2_rn(b, a);
    uint2 q;
    q.x = *reinterpret_cast<const unsigned int*>(&h0);
    q.y = *reinterpret_cast<const unsigned int*>(&h1);
    g_tplh[idx] = q;
}

__device__ __forceinline__ void cp_async16(uint32_t saddr, const void* gaddr)
{
    asm volatile("cp.async.cg.shared.global [%0], [%1], 16;\n" :: "r"(saddr), "l"(gaddr));
}
__device__ __forceinline__ void cp_commit()  { asm volatile("cp.async.commit_group;\n" ::: "memory"); }
__device__ __forceinline__ void cp_wait0()   { asm volatile("cp.async.wait_group 0;\n" ::: "memory"); }

__device__ __forceinline__ void vox_unpack(const uint2 q, float& r, float& g, float& b, float& a)
{
    const half2 h0 = *reinterpret_cast<const half2*>(&q.x);
    const half2 h1 = *reinterpret_cast<const half2*>(&q.y);
    const float2 f0 = __half22float2(h0);
    const float2 f1 = __half22float2(h1);
    r = f0.x; g = f0.y; b = f1.x; a = f1.y;
}

__global__ void __launch_bounds__(NTHREADS, 1)
raymarch_kernel(const float* __restrict__ raypos,
                const float* __restrict__ raydir,
                const float* __restrict__ tminmax,
                const float* __restrict__ primpos,
                const float* __restrict__ primrot,
                const float* __restrict__ primscale,
                float* __restrict__ out)
{
    extern __shared__ uint2 smbuf[];                 // [2][4096]
    float* Mc = (float*)(smbuf + 2 * VOX_PER_PRIM);  // [32][12]

    const int tid  = threadIdx.x;
    const int lane = tid & 31;
    const int w    = tid >> 5;                       // warp = local ray
    const int r    = blockIdx.x * RAYS_PER_BLOCK + w;

    // warp-uniform ray data (broadcast loads: all lanes same address)
    const float rpx = raypos[3*r+0], rpy = raypos[3*r+1], rpz = raypos[3*r+2];
    const float rdx = raydir[3*r+0], rdy = raydir[3*r+1], rdz = raydir[3*r+2];
    const float tmn = tminmax[2*r+0], tmx = tminmax[2*r+1];

    // Per-prim affine: yloc_i = M[i]·pos - c_i, M[i][j] = scale_i * rot[i][j]
    if (tid < NK) {
        const int k = tid;
        const float ppx = primpos[3*k+0], ppy = primpos[3*k+1], ppz = primpos[3*k+2];
        #pragma unroll
        for (int i = 0; i < 3; i++) {
            const float s  = primscale[3*k+i];
            const float m0 = s * primrot[9*k+3*i+0];
            const float m1 = s * primrot[9*k+3*i+1];
            const float m2 = s * primrot[9*k+3*i+2];
            Mc[12*k+4*i+0] = m0;
            Mc[12*k+4*i+1] = m1;
            Mc[12*k+4*i+2] = m2;
            Mc[12*k+4*i+3] = m0*ppx + m1*ppy + m2*ppz;
        }
    }

    // Thread owns steps (lane) and (lane+32): t0, t1
    const float tA = fmaf((float)lane, DT_F, tmn);
    const float tB = fmaf((float)(lane + 32), DT_F, tmn);
    float px[2], py[2], pz[2];
    px[0] = fmaf(rdx, tA, rpx); py[0] = fmaf(rdy, tA, rpy); pz[0] = fmaf(rdz, tA, rpz);
    px[1] = fmaf(rdx, tB, rpx); py[1] = fmaf(rdy, tB, rpy); pz[1] = fmaf(rdz, tB, rpz);

    float4 acc[2];
    acc[0] = make_float4(0.f, 0.f, 0.f, 0.f);
    acc[1] = make_float4(0.f, 0.f, 0.f, 0.f);

    // warp-uniform ray t-window
    const float tray_lo = tmn;
    const float tray_hi = fmaf(63.f, DT_F, tmn);
    const float EPS = 1e-5f;

    const uint32_t sm_base = (uint32_t)__cvta_generic_to_shared(smbuf);

    // Prefetch prim 0 into buffer 0 (16B = 2 voxels per cp.async; 2048 chunks)
    {
        const uint2* src = g_tplh;                    // prim 0
        cp_async16(sm_base + (uint32_t)(tid * 16),              src + tid * 2);
        cp_async16(sm_base + (uint32_t)((tid + 1024) * 16),     src + (tid + 1024) * 2);
        cp_commit();
    }

    for (int k = 0; k < NK; k++) {
        const int cur = k & 1;
        cp_wait0();
        __syncthreads();   // buf[cur] fully staged; eval of buf[cur] (from k-1 round) done

        if (k + 1 < NK) {
            const uint2* src = g_tplh + (size_t)(k + 1) * VOX_PER_PRIM;
            const uint32_t dst = sm_base + (uint32_t)((k + 1) & 1) * (VOX_PER_PRIM * 8);
            cp_async16(dst + (uint32_t)(tid * 16),          src + tid * 2);
            cp_async16(dst + (uint32_t)((tid + 1024) * 16), src + (tid + 1024) * 2);
            cp_commit();
        }

        const uint2* __restrict__ tpl = smbuf + cur * VOX_PER_PRIM;

        const float m00 = Mc[12*k+0], m01 = Mc[12*k+1], m02 = Mc[12*k+2], c0 = Mc[12*k+3];
        const float m10 = Mc[12*k+4], m11 = Mc[12*k+5], m12 = Mc[12*k+6], c1 = Mc[12*k+7];
        const float m20 = Mc[12*k+8], m21 = Mc[12*k+9], m22 = Mc[12*k+10], c2 = Mc[12*k+11];

        // ---- Warp-uniform slab cull (all lanes share the ray, so this branch
        //      is uniform): yloc(t) = b + t*a per axis; inside iff |y|<=1. ----
        {
            const float a0 = fmaf(m00, rdx, fmaf(m01, rdy, m02*rdz));
            const float a1 = fmaf(m10, rdx, fmaf(m11, rdy, m12*rdz));
            const float a2 = fmaf(m20, rdx, fmaf(m21, rdy, m22*rdz));
            const float b0 = fmaf(m00, rpx, fmaf(m01, rpy, fmaf(m02, rpz, -c0)));
            const float b1 = fmaf(m10, rpx, fmaf(m11, rpy, fmaf(m12, rpz, -c1)));
            const float b2 = fmaf(m20, rpx, fmaf(m21, rpy, fmaf(m22, rpz, -c2)));

            const float i0 = 1.f / a0, i1 = 1.f / a1, i2 = 1.f / a2;
            const float u0 = (-1.f - EPS - b0) * i0, v0 = (1.f + EPS - b0) * i0;
            const float u1 = (-1.f - EPS - b1) * i1, v1 = (1.f + EPS - b1) * i1;
            const float u2 = (-1.f - EPS - b2) * i2, v2 = (1.f + EPS - b2) * i2;
            const float tlo = fmaxf(fmaxf(fminf(u0, v0), fminf(u1, v1)), fminf(u2, v2));
            const float thi = fminf(fminf(fmaxf(u0, v0), fmaxf(u1, v1)), fmaxf(u2, v2));

            if (!(thi < tray_lo || tlo > tray_hi || tlo > thi)) {
                #pragma unroll
                for (int j = 0; j < 2; j++) {
                    const float t = (j == 0) ? tA : tB;
                    if (t < tlo || t > thi) continue;

                    const float y0 = fmaf(m00, px[j], fmaf(m01, py[j], fmaf(m02, pz[j], -c0)));
                    const float y1 = fmaf(m10, px[j], fmaf(m11, py[j], fmaf(m12, pz[j], -c1)));
                    const float y2 = fmaf(m20, px[j], fmaf(m21, py[j], fmaf(m22, pz[j], -c2)));

                    if (fabsf(y0) <= 1.f && fabsf(y1) <= 1.f && fabsf(y2) <= 1.f) {
                        const float gz = fmaf(y0, 7.5f, 7.5f);
                        const float gy = fmaf(y1, 7.5f, 7.5f);
                        const float gx = fmaf(y2, 7.5f, 7.5f);
                        const float fz0 = fminf(floorf(gz), 14.f);
                        const float fy0 = fminf(floorf(gy), 14.f);
                        const float fx0 = fminf(floorf(gx), 14.f);
                        const int iz = (int)fz0, iy = (int)fy0, ix = (int)fx0;
                        const float fz = fminf(gz - fz0, 1.f);
                        const float fy = fminf(gy - fy0, 1.f);
                        const float fx = fminf(gx - fx0, 1.f);

                        const int base = (iz*16 + iy)*16 + ix;
                        const uint2 q000 = tpl[base],       q001 = tpl[base + 1];
                        const uint2 q010 = tpl[base + 16],  q011 = tpl[base + 17];
                        const uint2 q100 = tpl[base + 256], q101 = tpl[base + 257];
                        const uint2 q110 = tpl[base + 272], q111 = tpl[base + 273];

                        const float wz0 = 1.f - fz, wy0 = 1.f - fy, wx0 = 1.f - fx;
                        const float w00 = wz0*wy0, w01 = wz0*fy, w10 = fz*wy0, w11 = fz*fy;
                        const float w000 = w00*wx0, w001 = w00*fx;
                        const float w010 = w01*wx0, w011 = w01*fx;
                        const float w100 = w10*wx0, w101 = w10*fx;
                        const float w110 = w11*wx0, w111 = w11*fx;

                        float vr, vg, vb, va;
                        float ax = acc[j].x, ay = acc[j].y, az = acc[j].z, aw = acc[j].w;
                        vox_unpack(q000, vr, vg, vb, va);
                        ax = fmaf(w000, vr, ax); ay = fmaf(w000, vg, ay);
                        az = fmaf(w000, vb, az); aw = fmaf(w000, va, aw);
                        vox_unpack(q001, vr, vg, vb, va);
                        ax = fmaf(w001, vr, ax); ay = fmaf(w001, vg, ay);
                        az = fmaf(w001, vb, az); aw = fmaf(w001, va, aw);
                        vox_unpack(q010, vr, vg, vb, va);
                        ax = fmaf(w010, vr, ax); ay = fmaf(w010, vg, ay);
                        az = fmaf(w010, vb, az); aw = fmaf(w010, va, aw);
                        vox_unpack(q011, vr, vg, vb, va);
                        ax = fmaf(w011, vr, ax); ay = fmaf(w011, vg, ay);
                        az = fmaf(w011, vb, az); aw = fmaf(w011, va, aw);
                        vox_unpack(q100, vr, vg, vb, va);
                        ax = fmaf(w100, vr, ax); ay = fmaf(w100, vg, ay);
                        az = fmaf(w100, vb, az); aw = fmaf(w100, va, aw);
                        vox_unpack(q101, vr, vg, vb, va);
                        ax = fmaf(w101, vr, ax); ay = fmaf(w101, vg, ay);
                        az = fmaf(w101, vb, az); aw = fmaf(w101, va, aw);
                        vox_unpack(q110, vr, vg, vb, va);
                        ax = fmaf(w110, vr, ax); ay = fmaf(w110, vg, ay);
                        az = fmaf(w110, vb, az); aw = fmaf(w110, va, aw);
                        vox_unpack(q111, vr, vg, vb, va);
                        ax = fmaf(w111, vr, ax); ay = fmaf(w111, vg, ay);
                        az = fmaf(w111, vb, az); aw = fmaf(w111, va, aw);
                        acc[j].x = ax; acc[j].y = ay; acc[j].z = az; acc[j].w = aw;
                    }
                }
            }
        }
        __syncthreads();   // everyone done with buf[cur] before it is refilled (k+2)
    }

    // ---- Composite: alpha_i = min(prefix_i, 1); contrib_i = alpha_i - alpha_{i-1}.
    //      Steps 0..31 = lanes at j=0; steps 32..63 = lanes at j=1. ----
    const float sA = (tA < tmx) ? acc[0].w * DT_F : 0.f;
    const float sB = (tB < tmx) ? acc[1].w * DT_F : 0.f;

    // inclusive width-32 scan of sA
    float scanA = sA;
    #pragma unroll
    for (int d = 1; d < 32; d <<= 1) {
        const float v = __shfl_up_sync(0xffffffffu, scanA, d);
        if (lane >= d) scanA += v;
    }
    const float totA = __shfl_sync(0xffffffffu, scanA, 31);

    // inclusive width-32 scan of sB
    float scanB = sB;
    #pragma unroll
    for (int d = 1; d < 32; d <<= 1) {
        const float v = __shfl_up_sync(0xffffffffu, scanB, d);
        if (lane >= d) scanB += v;
    }

    const float PA = scanA;                 // inclusive prefix at step lane
    const float PB = totA + scanB;          // inclusive prefix at step lane+32

    const float contribA = fminf(PA, 1.f) - fminf(PA - sA, 1.f);
    const float contribB = fminf(PB, 1.f) - fminf(PB - sB, 1.f);

    float rgbx = acc[0].x * contribA + acc[1].x * contribB;
    float rgby = acc[0].y * contribA + acc[1].y * contribB;
    float rgbz = acc[0].z * contribA + acc[1].z * contribB;

    #pragma unroll
    for (int d = 16; d >= 1; d >>= 1) {
        rgbx += __shfl_xor_sync(0xffffffffu, rgbx, d);
        rgby += __shfl_xor_sync(0xffffffffu, rgby, d);
        rgbz += __shfl_xor_sync(0xffffffffu, rgbz, d);
    }
    const float alpha_final = fminf(totA + __shfl_sync(0xffffffffu, scanB, 31), 1.f);

    if (lane == 0) {
        // out = [rayrgb (3*R)] [rayalpha (R)] [rayrgba (4*R)]
        out[0*RTOT + r] = rgbx;
        out[1*RTOT + r] = rgby;
        out[2*RTOT + r] = rgbz;
        out[3*RTOT + r] = alpha_final;
        out[4*RTOT + r] = rgbx;
        out[5*RTOT + r] = rgby;
        out[6*RTOT + r] = rgbz;
        out[7*RTOT + r] = alpha_final;
    }
}

extern "C" void kernel_launch(void* const* d_in, const int* in_sizes, int n_in,
                              void* d_out, int out_size)
{
    const float* raypos    = (const float*)d_in[0];
    const float* raydir    = (const float*)d_in[1];
    const float* tminmax   = (const float*)d_in[2];
    const float* primpos   = (const float*)d_in[3];
    const float* primrot   = (const float*)d_in[4];
    const float* primscale = (const float*)d_in[5];
    const float* tpl       = (const float*)d_in[6];
    float* out = (float*)d_out;

    convert_tpl_kernel<<<NK * VOX_PER_PRIM / 256, 256>>>(tpl);

    cudaFuncSetAttribute(raymarch_kernel,
                         cudaFuncAttributeMaxDynamicSharedMemorySize, SMEM_BYTES);

    raymarch_kernel<<<NBLOCKS, NTHREADS, SMEM_BYTES>>>(
        raypos, raydir, tminmax, primpos, primrot, primscale, out);
}

// round 8
// speedup vs baseline: 1.0623x; 1.0623x over previous
#include <cuda_runtime.h>
#include <cuda_fp16.h>
#include <cstdint>

#define DT_F (1.0f/64.0f)
#define NSTEPS 64
#define NK 32
#define RTOT 16384
#define RAYS_PER_BLOCK 32
#define NTHREADS 1024
#define NBLOCKS (RTOT / RAYS_PER_BLOCK)         // 512
#define VOX_PER_PRIM 4096
#define PRIM_BYTES (VOX_PER_PRIM * 8)           // 32 KB (fp16x4 voxels)
// dynamic smem: 2 x 32KB template buffers + 2 mbarriers + 32*12 floats affine
#define SMEM_BYTES (2 * PRIM_BYTES + 16 + NK * 12 * 4)

// fp16-packed template: [k][z][y][x] -> uint2 (r,g | b,a as half2)
__device__ __align__(16) uint2 g_tplh[NK * VOX_PER_PRIM];

__global__ void convert_tpl_kernel(const float* __restrict__ tpl)
{
    const int idx = blockIdx.x * blockDim.x + threadIdx.x;   // 0 .. 131071
    const int k = idx >> 12;
    const int v = idx & 4095;
    const float* tk = tpl + (size_t)k * 4 * VOX_PER_PRIM;
    const float r = tk[v];
    const float g = tk[v + 4096];
    const float b = tk[v + 8192];
    const float a = tk[v + 12288];
    const half2 h0 = __floats2half2_rn(r, g);
    const half2 h1 = __floats2half2_rn(b, a);
    uint2 q;
    q.x = *reinterpret_cast<const unsigned int*>(&h0);
    q.y = *reinterpret_cast<const unsigned int*>(&h1);
    g_tplh[idx] = q;
}

__device__ __forceinline__ void mbar_init(uint32_t mbar, uint32_t count)
{
    asm volatile("mbarrier.init.shared.b64 [%0], %1;" :: "r"(mbar), "r"(count) : "memory");
}
__device__ __forceinline__ void mbar_expect_tx(uint32_t mbar, uint32_t bytes)
{
    asm volatile("mbarrier.arrive.expect_tx.shared.b64 _, [%0], %1;" :: "r"(mbar), "r"(bytes) : "memory");
}
__device__ __forceinline__ void mbar_wait(uint32_t mbar, uint32_t phase)
{
    asm volatile(
        "{\n\t"
        ".reg .pred P;\n\t"
        "WAIT_%=:\n\t"
        "mbarrier.try_wait.parity.acquire.cta.shared::cta.b64 P, [%0], %1, 0x989680;\n\t"
        "@P bra DONE_%=;\n\t"
        "bra.uni WAIT_%=;\n\t"
        "DONE_%=:\n\t"
        "}"
        :: "r"(mbar), "r"(phase) : "memory");
}
__device__ __forceinline__ void bulk_copy(uint32_t dst_smem, const void* src, uint32_t bytes, uint32_t mbar)
{
    asm volatile(
        "cp.async.bulk.shared::cta.global.mbarrier::complete_tx::bytes [%0], [%1], %2, [%3];"
        :: "r"(dst_smem), "l"(src), "r"(bytes), "r"(mbar) : "memory");
}

__device__ __forceinline__ void vox_unpack(const uint2 q, float& r, float& g, float& b, float& a)
{
    const half2 h0 = *reinterpret_cast<const half2*>(&q.x);
    const half2 h1 = *reinterpret_cast<const half2*>(&q.y);
    const float2 f0 = __half22float2(h0);
    const float2 f1 = __half22float2(h1);
    r = f0.x; g = f0.y; b = f1.x; a = f1.y;
}

__global__ void __launch_bounds__(NTHREADS, 1)
raymarch_kernel(const float* __restrict__ raypos,
                const float* __restrict__ raydir,
                const float* __restrict__ tminmax,
                const float* __restrict__ primpos,
                const float* __restrict__ primrot,
                const float* __restrict__ primscale,
                float* __restrict__ out)
{
    extern __shared__ __align__(16) uint2 smbuf[];      // [2][4096]
    uint64_t* mbar64 = (uint64_t*)(smbuf + 2 * VOX_PER_PRIM);   // 2 mbarriers
    float* Mc = (float*)(mbar64 + 2);                   // [32][12]

    const int tid  = threadIdx.x;
    const int lane = tid & 31;
    const int w    = tid >> 5;                          // warp = local ray
    const int r    = blockIdx.x * RAYS_PER_BLOCK + w;

    const uint32_t sm_base   = (uint32_t)__cvta_generic_to_shared(smbuf);
    const uint32_t mbar_base = (uint32_t)__cvta_generic_to_shared(mbar64);

    // warp-uniform ray data (broadcast loads: all lanes same address)
    const float rpx = raypos[3*r+0], rpy = raypos[3*r+1], rpz = raypos[3*r+2];
    const float rdx = raydir[3*r+0], rdy = raydir[3*r+1], rdz = raydir[3*r+2];
    const float tmn = tminmax[2*r+0], tmx = tminmax[2*r+1];

    // Per-prim affine: yloc_i = M[i]·pos - c_i, M[i][j] = scale_i * rot[i][j]
    if (tid < NK) {
        const int k = tid;
        const float ppx = primpos[3*k+0], ppy = primpos[3*k+1], ppz = primpos[3*k+2];
        #pragma unroll
        for (int i = 0; i < 3; i++) {
            const float s  = primscale[3*k+i];
            const float m0 = s * primrot[9*k+3*i+0];
            const float m1 = s * primrot[9*k+3*i+1];
            const float m2 = s * primrot[9*k+3*i+2];
            Mc[12*k+4*i+0] = m0;
            Mc[12*k+4*i+1] = m1;
            Mc[12*k+4*i+2] = m2;
            Mc[12*k+4*i+3] = m0*ppx + m1*ppy + m2*ppz;
        }
    }

    if (tid == 0) {
        mbar_init(mbar_base + 0, 1);
        mbar_init(mbar_base + 8, 1);
    }
    __syncthreads();     // Mc + mbarrier init visible to all

    // Kick off prim 0 into buffer 0 (single TMA bulk copy)
    if (tid == 0) {
        mbar_expect_tx(mbar_base + 0, PRIM_BYTES);
        bulk_copy(sm_base, g_tplh, PRIM_BYTES, mbar_base + 0);
    }

    // Thread owns steps (lane) and (lane+32): tA, tB
    const float tA = fmaf((float)lane, DT_F, tmn);
    const float tB = fmaf((float)(lane + 32), DT_F, tmn);
    float px[2], py[2], pz[2];
    px[0] = fmaf(rdx, tA, rpx); py[0] = fmaf(rdy, tA, rpy); pz[0] = fmaf(rdz, tA, rpz);
    px[1] = fmaf(rdx, tB, rpx); py[1] = fmaf(rdy, tB, rpy); pz[1] = fmaf(rdz, tB, rpz);

    float4 acc[2];
    acc[0] = make_float4(0.f, 0.f, 0.f, 0.f);
    acc[1] = make_float4(0.f, 0.f, 0.f, 0.f);

    // warp-uniform ray t-window
    const float tray_lo = tmn;
    const float tray_hi = fmaf(63.f, DT_F, tmn);
    const float EPS = 1e-5f;

    int ph0 = 0, ph1 = 0;

    for (int k = 0; k < NK; k++) {
        const int cur = k & 1;
        // wait buf[cur] filled (TMA completion)
        if (cur == 0) { mbar_wait(mbar_base + 0, ph0); ph0 ^= 1; }
        else          { mbar_wait(mbar_base + 8, ph1); ph1 ^= 1; }
        __syncthreads();   // all threads done with prim k-1 eval (buf[nxt] reusable)

        if (k + 1 < NK && tid == 0) {
            const int nxt = (k + 1) & 1;
            mbar_expect_tx(mbar_base + 8u * nxt, PRIM_BYTES);
            bulk_copy(sm_base + (uint32_t)nxt * PRIM_BYTES,
                      g_tplh + (size_t)(k + 1) * VOX_PER_PRIM,
                      PRIM_BYTES, mbar_base + 8u * nxt);
        }

        const uint2* __restrict__ tpl = smbuf + cur * VOX_PER_PRIM;

        const float m00 = Mc[12*k+0], m01 = Mc[12*k+1], m02 = Mc[12*k+2], c0 = Mc[12*k+3];
        const float m10 = Mc[12*k+4], m11 = Mc[12*k+5], m12 = Mc[12*k+6], c1 = Mc[12*k+7];
        const float m20 = Mc[12*k+8], m21 = Mc[12*k+9], m22 = Mc[12*k+10], c2 = Mc[12*k+11];

        // ---- Warp-uniform slab cull (all lanes share the ray): yloc(t)=b+t*a ----
        {
            const float a0 = fmaf(m00, rdx, fmaf(m01, rdy, m02*rdz));
            const float a1 = fmaf(m10, rdx, fmaf(m11, rdy, m12*rdz));
            const float a2 = fmaf(m20, rdx, fmaf(m21, rdy, m22*rdz));
            const float b0 = fmaf(m00, rpx, fmaf(m01, rpy, fmaf(m02, rpz, -c0)));
            const float b1 = fmaf(m10, rpx, fmaf(m11, rpy, fmaf(m12, rpz, -c1)));
            const float b2 = fmaf(m20, rpx, fmaf(m21, rpy, fmaf(m22, rpz, -c2)));

            const float i0 = 1.f / a0, i1 = 1.f / a1, i2 = 1.f / a2;
            const float u0 = (-1.f - EPS - b0) * i0, v0 = (1.f + EPS - b0) * i0;
            const float u1 = (-1.f - EPS - b1) * i1, v1 = (1.f + EPS - b1) * i1;
            const float u2 = (-1.f - EPS - b2) * i2, v2 = (1.f + EPS - b2) * i2;
            const float tlo = fmaxf(fmaxf(fminf(u0, v0), fminf(u1, v1)), fminf(u2, v2));
            const float thi = fminf(fminf(fmaxf(u0, v0), fmaxf(u1, v1)), fmaxf(u2, v2));

            if (!(thi < tray_lo || tlo > tray_hi || tlo > thi)) {
                #pragma unroll
                for (int j = 0; j < 2; j++) {
                    const float t = (j == 0) ? tA : tB;
                    if (t < tlo || t > thi) continue;

                    const float y0 = fmaf(m00, px[j], fmaf(m01, py[j], fmaf(m02, pz[j], -c0)));
                    const float y1 = fmaf(m10, px[j], fmaf(m11, py[j], fmaf(m12, pz[j], -c1)));
                    const float y2 = fmaf(m20, px[j], fmaf(m21, py[j], fmaf(m22, pz[j], -c2)));

                    if (fabsf(y0) <= 1.f && fabsf(y1) <= 1.f && fabsf(y2) <= 1.f) {
                        const float gz = fmaf(y0, 7.5f, 7.5f);
                        const float gy = fmaf(y1, 7.5f, 7.5f);
                        const float gx = fmaf(y2, 7.5f, 7.5f);
                        const float fz0 = fminf(floorf(gz), 14.f);
                        const float fy0 = fminf(floorf(gy), 14.f);
                        const float fx0 = fminf(floorf(gx), 14.f);
                        const int iz = (int)fz0, iy = (int)fy0, ix = (int)fx0;
                        const float fz = fminf(gz - fz0, 1.f);
                        const float fy = fminf(gy - fy0, 1.f);
                        const float fx = fminf(gx - fx0, 1.f);

                        const int base = (iz*16 + iy)*16 + ix;
                        const uint2 q000 = tpl[base],       q001 = tpl[base + 1];
                        const uint2 q010 = tpl[base + 16],  q011 = tpl[base + 17];
                        const uint2 q100 = tpl[base + 256], q101 = tpl[base + 257];
                        const uint2 q110 = tpl[base + 272], q111 = tpl[base + 273];

                        const float wz0 = 1.f - fz, wy0 = 1.f - fy, wx0 = 1.f - fx;
                        const float w00 = wz0*wy0, w01 = wz0*fy, w10 = fz*wy0, w11 = fz*fy;
                        const float w000 = w00*wx0, w001 = w00*fx;
                        const float w010 = w01*wx0, w011 = w01*fx;
                        const float w100 = w10*wx0, w101 = w10*fx;
                        const float w110 = w11*wx0, w111 = w11*fx;

                        float vr, vg, vb, va;
                        float ax = acc[j].x, ay = acc[j].y, az = acc[j].z, aw = acc[j].w;
                        vox_unpack(q000, vr, vg, vb, va);
                        ax = fmaf(w000, vr, ax); ay = fmaf(w000, vg, ay);
                        az = fmaf(w000, vb, az); aw = fmaf(w000, va, aw);
                        vox_unpack(q001, vr, vg, vb, va);
                        ax = fmaf(w001, vr, ax); ay = fmaf(w001, vg, ay);
                        az = fmaf(w001, vb, az); aw = fmaf(w001, va, aw);
                        vox_unpack(q010, vr, vg, vb, va);
                        ax = fmaf(w010, vr, ax); ay = fmaf(w010, vg, ay);
                        az = fmaf(w010, vb, az); aw = fmaf(w010, va, aw);
                        vox_unpack(q011, vr, vg, vb, va);
                        ax = fmaf(w011, vr, ax); ay = fmaf(w011, vg, ay);
                        az = fmaf(w011, vb, az); aw = fmaf(w011, va, aw);
                        vox_unpack(q100, vr, vg, vb, va);
                        ax = fmaf(w100, vr, ax); ay = fmaf(w100, vg, ay);
                        az = fmaf(w100, vb, az); aw = fmaf(w100, va, aw);
                        vox_unpack(q101, vr, vg, vb, va);
                        ax = fmaf(w101, vr, ax); ay = fmaf(w101, vg, ay);
                        az = fmaf(w101, vb, az); aw = fmaf(w101, va, aw);
                        vox_unpack(q110, vr, vg, vb, va);
                        ax = fmaf(w110, vr, ax); ay = fmaf(w110, vg, ay);
                        az = fmaf(w110, vb, az); aw = fmaf(w110, va, aw);
                        vox_unpack(q111, vr, vg, vb, va);
                        ax = fmaf(w111, vr, ax); ay = fmaf(w111, vg, ay);
                        az = fmaf(w111, vb, az); aw = fmaf(w111, va, aw);
                        acc[j].x = ax; acc[j].y = ay; acc[j].z = az; acc[j].w = aw;
                    }
                }
            }
        }
        // no trailing barrier: reuse of buf[cur] is gated by the __syncthreads()
        // at the top of iteration k+1 (all threads past eval of prim k).
    }

    // ---- Composite: alpha_i = min(prefix_i, 1); contrib_i = alpha_i - alpha_{i-1}.
    //      Steps 0..31 = lanes at j=0; steps 32..63 = lanes at j=1. ----
    const float sA = (tA < tmx) ? acc[0].w * DT_F : 0.f;
    const float sB = (tB < tmx) ? acc[1].w * DT_F : 0.f;

    float scanA = sA;
    #pragma unroll
    for (int d = 1; d < 32; d <<= 1) {
        const float v = __shfl_up_sync(0xffffffffu, scanA, d);
        if (lane >= d) scanA += v;
    }
    const float totA = __shfl_sync(0xffffffffu, scanA, 31);

    float scanB = sB;
    #pragma unroll
    for (int d = 1; d < 32; d <<= 1) {
        const float v = __shfl_up_sync(0xffffffffu, scanB, d);
        if (lane >= d) scanB += v;
    }

    const float PA = scanA;                 // inclusive prefix at step lane
    const float PB = totA + scanB;          // inclusive prefix at step lane+32

    const float contribA = fminf(PA, 1.f) - fminf(PA - sA, 1.f);
    const float contribB = fminf(PB, 1.f) - fminf(PB - sB, 1.f);

    float rgbx = acc[0].x * contribA + acc[1].x * contribB;
    float rgby = acc[0].y * contribA + acc[1].y * contribB;
    float rgbz = acc[0].z * contribA + acc[1].z * contribB;

    #pragma unroll
    for (int d = 16; d >= 1; d >>= 1) {
        rgbx += __shfl_xor_sync(0xffffffffu, rgbx, d);
        rgby += __shfl_xor_sync(0xffffffffu, rgby, d);
        rgbz += __shfl_xor_sync(0xffffffffu, rgbz, d);
    }
    const float alpha_final = fminf(totA + __shfl_sync(0xffffffffu, scanB, 31), 1.f);

    if (lane == 0) {
        // out = [rayrgb (3*R)] [rayalpha (R)] [rayrgba (4*R)]
        out[0*RTOT + r] = rgbx;
        out[1*RTOT + r] = rgby;
        out[2*RTOT + r] = rgbz;
        out[3*RTOT + r] = alpha_final;
        out[4*RTOT + r] = rgbx;
        out[5*RTOT + r] = rgby;
        out[6*RTOT + r] = rgbz;
        out[7*RTOT + r] = alpha_final;
    }
}

extern "C" void kernel_launch(void* const* d_in, const int* in_sizes, int n_in,
                              void* d_out, int out_size)
{
    const float* raypos    = (const float*)d_in[0];
    const float* raydir    = (const float*)d_in[1];
    const float* tminmax   = (const float*)d_in[2];
    const float* primpos   = (const float*)d_in[3];
    const float* primrot   = (const float*)d_in[4];
    const float* primscale = (const float*)d_in[5];
    const float* tpl       = (const float*)d_in[6];
    float* out = (float*)d_out;

    convert_tpl_kernel<<<NK * VOX_PER_PRIM / 256, 256>>>(tpl);

    cudaFuncSetAttribute(raymarch_kernel,
                         cudaFuncAttributeMaxDynamicSharedMemorySize, SMEM_BYTES);

    raymarch_kernel<<<NBLOCKS, NTHREADS, SMEM_BYTES>>>(
        raypos, raydir, tminmax, primpos, primrot, primscale, out);
}

// round 9
// speedup vs baseline: 1.5735x; 1.4813x over previous
#include <cuda_runtime.h>
#include <cuda_fp16.h>
#include <cstdint>

#define DT_F (1.0f/64.0f)
#define NSTEPS 64
#define NK 32
#define RTOT 16384
#define RAYS_PER_BLOCK 8
#define NTHREADS 256
#define NBLOCKS (RTOT / RAYS_PER_BLOCK)         // 2048
#define VOX_PER_PRIM 4096

// fp16-packed template: [k][z][y][x] -> uint2 (r,g | b,a as half2)
__device__ __align__(16) uint2 g_tplh[NK * VOX_PER_PRIM];

__global__ void convert_tpl_kernel(const float* __restrict__ tpl)
{
    const int idx = blockIdx.x * blockDim.x + threadIdx.x;   // 0 .. 131071
    const int k = idx >> 12;
    const int v = idx & 4095;
    const float* tk = tpl + (size_t)k * 4 * VOX_PER_PRIM;
    const float r = tk[v];
    const float g = tk[v + 4096];
    const float b = tk[v + 8192];
    const float a = tk[v + 12288];
    const half2 h0 = __floats2half2_rn(r, g);
    const half2 h1 = __floats2half2_rn(b, a);
    uint2 q;
    q.x = *reinterpret_cast<const unsigned int*>(&h0);
    q.y = *reinterpret_cast<const unsigned int*>(&h1);
    g_tplh[idx] = q;
}

__device__ __forceinline__ void vox_unpack(const uint2 q, float& r, float& g, float& b, float& a)
{
    const half2 h0 = *reinterpret_cast<const half2*>(&q.x);
    const half2 h1 = *reinterpret_cast<const half2*>(&q.y);
    const float2 f0 = __half22float2(h0);
    const float2 f1 = __half22float2(h1);
    r = f0.x; g = f0.y; b = f1.x; a = f1.y;
}

__global__ void __launch_bounds__(NTHREADS)
raymarch_kernel(const float* __restrict__ raypos,
                const float* __restrict__ raydir,
                const float* __restrict__ tminmax,
                const float* __restrict__ primpos,
                const float* __restrict__ primrot,
                const float* __restrict__ primscale,
                float* __restrict__ out)
{
    __shared__ float Mc[NK * 12];       // per-prim affine rows (m0,m1,m2,c)

    const int tid  = threadIdx.x;
    const int lane = tid & 31;
    const int w    = tid >> 5;                          // warp = local ray
    const int r    = blockIdx.x * RAYS_PER_BLOCK + w;

    // warp-uniform ray data (broadcast loads: all lanes same address)
    const float rpx = raypos[3*r+0], rpy = raypos[3*r+1], rpz = raypos[3*r+2];
    const float rdx = raydir[3*r+0], rdy = raydir[3*r+1], rdz = raydir[3*r+2];
    const float tmn = tminmax[2*r+0], tmx = tminmax[2*r+1];

    // Per-prim affine: yloc_i = M[i]·pos - c_i, M[i][j] = scale_i * rot[i][j]
    if (tid < NK) {
        const int k = tid;
        const float ppx = primpos[3*k+0], ppy = primpos[3*k+1], ppz = primpos[3*k+2];
        #pragma unroll
        for (int i = 0; i < 3; i++) {
            const float s  = primscale[3*k+i];
            const float m0 = s * primrot[9*k+3*i+0];
            const float m1 = s * primrot[9*k+3*i+1];
            const float m2 = s * primrot[9*k+3*i+2];
            Mc[12*k+4*i+0] = m0;
            Mc[12*k+4*i+1] = m1;
            Mc[12*k+4*i+2] = m2;
            Mc[12*k+4*i+3] = m0*ppx + m1*ppy + m2*ppz;
        }
    }
    __syncthreads();    // only block-wide sync in the kernel

    // Thread owns steps (lane) and (lane+32): tA, tB
    const float tA = fmaf((float)lane, DT_F, tmn);
    const float tB = fmaf((float)(lane + 32), DT_F, tmn);
    float px[2], py[2], pz[2];
    px[0] = fmaf(rdx, tA, rpx); py[0] = fmaf(rdy, tA, rpy); pz[0] = fmaf(rdz, tA, rpz);
    px[1] = fmaf(rdx, tB, rpx); py[1] = fmaf(rdy, tB, rpy); pz[1] = fmaf(rdz, tB, rpz);

    float4 acc[2];
    acc[0] = make_float4(0.f, 0.f, 0.f, 0.f);
    acc[1] = make_float4(0.f, 0.f, 0.f, 0.f);

    // warp-uniform ray t-window
    const float tray_lo = tmn;
    const float tray_hi = fmaf(63.f, DT_F, tmn);
    const float EPS = 1e-5f;

    for (int k = 0; k < NK; k++) {
        const uint2* __restrict__ tpl = g_tplh + (size_t)k * VOX_PER_PRIM;

        const float m00 = Mc[12*k+0], m01 = Mc[12*k+1], m02 = Mc[12*k+2], c0 = Mc[12*k+3];
        const float m10 = Mc[12*k+4], m11 = Mc[12*k+5], m12 = Mc[12*k+6], c1 = Mc[12*k+7];
        const float m20 = Mc[12*k+8], m21 = Mc[12*k+9], m22 = Mc[12*k+10], c2 = Mc[12*k+11];

        // ---- Warp-uniform slab cull (all lanes share the ray): yloc(t)=b+t*a ----
        const float a0 = fmaf(m00, rdx, fmaf(m01, rdy, m02*rdz));
        const float a1 = fmaf(m10, rdx, fmaf(m11, rdy, m12*rdz));
        const float a2 = fmaf(m20, rdx, fmaf(m21, rdy, m22*rdz));
        const float b0 = fmaf(m00, rpx, fmaf(m01, rpy, fmaf(m02, rpz, -c0)));
        const float b1 = fmaf(m10, rpx, fmaf(m11, rpy, fmaf(m12, rpz, -c1)));
        const float b2 = fmaf(m20, rpx, fmaf(m21, rpy, fmaf(m22, rpz, -c2)));

        const float i0 = 1.f / a0, i1 = 1.f / a1, i2 = 1.f / a2;
        const float u0 = (-1.f - EPS - b0) * i0, v0 = (1.f + EPS - b0) * i0;
        const float u1 = (-1.f - EPS - b1) * i1, v1 = (1.f + EPS - b1) * i1;
        const float u2 = (-1.f - EPS - b2) * i2, v2 = (1.f + EPS - b2) * i2;
        const float tlo = fmaxf(fmaxf(fminf(u0, v0), fminf(u1, v1)), fminf(u2, v2));
        const float thi = fminf(fminf(fmaxf(u0, v0), fmaxf(u1, v1)), fmaxf(u2, v2));

        if (thi < tray_lo || tlo > tray_hi || tlo > thi) continue;   // warp-uniform skip

        #pragma unroll
        for (int j = 0; j < 2; j++) {
            const float t = (j == 0) ? tA : tB;
            if (t < tlo || t > thi) continue;

            const float y0 = fmaf(m00, px[j], fmaf(m01, py[j], fmaf(m02, pz[j], -c0)));
            const float y1 = fmaf(m10, px[j], fmaf(m11, py[j], fmaf(m12, pz[j], -c1)));
            const float y2 = fmaf(m20, px[j], fmaf(m21, py[j], fmaf(m22, pz[j], -c2)));

            if (fabsf(y0) <= 1.f && fabsf(y1) <= 1.f && fabsf(y2) <= 1.f) {
                const float gz = fmaf(y0, 7.5f, 7.5f);
                const float gy = fmaf(y1, 7.5f, 7.5f);
                const float gx = fmaf(y2, 7.5f, 7.5f);
                const float fz0 = fminf(floorf(gz), 14.f);
                const float fy0 = fminf(floorf(gy), 14.f);
                const float fx0 = fminf(floorf(gx), 14.f);
                const int iz = (int)fz0, iy = (int)fy0, ix = (int)fx0;
                const float fz = fminf(gz - fz0, 1.f);
                const float fy = fminf(gy - fy0, 1.f);
                const float fx = fminf(gx - fx0, 1.f);

                const int base = (iz*16 + iy)*16 + ix;
                const uint2 q000 = __ldg(tpl + base);
                const uint2 q001 = __ldg(tpl + base + 1);
                const uint2 q010 = __ldg(tpl + base + 16);
                const uint2 q011 = __ldg(tpl + base + 17);
                const uint2 q100 = __ldg(tpl + base + 256);
                const uint2 q101 = __ldg(tpl + base + 257);
                const uint2 q110 = __ldg(tpl + base + 272);
                const uint2 q111 = __ldg(tpl + base + 273);

                const float wz0 = 1.f - fz, wy0 = 1.f - fy, wx0 = 1.f - fx;
                const float w00 = wz0*wy0, w01 = wz0*fy, w10 = fz*wy0, w11 = fz*fy;
                const float w000 = w00*wx0, w001 = w00*fx;
                const float w010 = w01*wx0, w011 = w01*fx;
                const float w100 = w10*wx0, w101 = w10*fx;
                const float w110 = w11*wx0, w111 = w11*fx;

                float vr, vg, vb, va;
                float ax = acc[j].x, ay = acc[j].y, az = acc[j].z, aw = acc[j].w;
                vox_unpack(q000, vr, vg, vb, va);
                ax = fmaf(w000, vr, ax); ay = fmaf(w000, vg, ay);
                az = fmaf(w000, vb, az); aw = fmaf(w000, va, aw);
                vox_unpack(q001, vr, vg, vb, va);
                ax = fmaf(w001, vr, ax); ay = fmaf(w001, vg, ay);
                az = fmaf(w001, vb, az); aw = fmaf(w001, va, aw);
                vox_unpack(q010, vr, vg, vb, va);
                ax = fmaf(w010, vr, ax); ay = fmaf(w010, vg, ay);
                az = fmaf(w010, vb, az); aw = fmaf(w010, va, aw);
                vox_unpack(q011, vr, vg, vb, va);
                ax = fmaf(w011, vr, ax); ay = fmaf(w011, vg, ay);
                az = fmaf(w011, vb, az); aw = fmaf(w011, va, aw);
                vox_unpack(q100, vr, vg, vb, va);
                ax = fmaf(w100, vr, ax); ay = fmaf(w100, vg, ay);
                az = fmaf(w100, vb, az); aw = fmaf(w100, va, aw);
                vox_unpack(q101, vr, vg, vb, va);
                ax = fmaf(w101, vr, ax); ay = fmaf(w101, vg, ay);
                az = fmaf(w101, vb, az); aw = fmaf(w101, va, aw);
                vox_unpack(q110, vr, vg, vb, va);
                ax = fmaf(w110, vr, ax); ay = fmaf(w110, vg, ay);
                az = fmaf(w110, vb, az); aw = fmaf(w110, va, aw);
                vox_unpack(q111, vr, vg, vb, va);
                ax = fmaf(w111, vr, ax); ay = fmaf(w111, vg, ay);
                az = fmaf(w111, vb, az); aw = fmaf(w111, va, aw);
                acc[j].x = ax; acc[j].y = ay; acc[j].z = az; acc[j].w = aw;
            }
        }
    }

    // ---- Composite: alpha_i = min(prefix_i, 1); contrib_i = alpha_i - alpha_{i-1}.
    //      Steps 0..31 = lanes at j=0; steps 32..63 = lanes at j=1. ----
    const float sA = (tA < tmx) ? acc[0].w * DT_F : 0.f;
    const float sB = (tB < tmx) ? acc[1].w * DT_F : 0.f;

    float scanA = sA;
    #pragma unroll
    for (int d = 1; d < 32; d <<= 1) {
        const float v = __shfl_up_sync(0xffffffffu, scanA, d);
        if (lane >= d) scanA += v;
    }
    const float totA = __shfl_sync(0xffffffffu, scanA, 31);

    float scanB = sB;
    #pragma unroll
    for (int d = 1; d < 32; d <<= 1) {
        const float v = __shfl_up_sync(0xffffffffu, scanB, d);
        if (lane >= d) scanB += v;
    }

    const float PA = scanA;                 // inclusive prefix at step lane
    const float PB = totA + scanB;          // inclusive prefix at step lane+32

    const float contribA = fminf(PA, 1.f) - fminf(PA - sA, 1.f);
    const float contribB = fminf(PB, 1.f) - fminf(PB - sB, 1.f);

    float rgbx = acc[0].x * contribA + acc[1].x * contribB;
    float rgby = acc[0].y * contribA + acc[1].y * contribB;
    float rgbz = acc[0].z * contribA + acc[1].z * contribB;

    #pragma unroll
    for (int d = 16; d >= 1; d >>= 1) {
        rgbx += __shfl_xor_sync(0xffffffffu, rgbx, d);
        rgby += __shfl_xor_sync(0xffffffffu, rgby, d);
        rgbz += __shfl_xor_sync(0xffffffffu, rgbz, d);
    }
    const float alpha_final = fminf(totA + __shfl_sync(0xffffffffu, scanB, 31), 1.f);

    if (lane == 0) {
        // out = [rayrgb (3*R)] [rayalpha (R)] [rayrgba (4*R)]
        out[0*RTOT + r] = rgbx;
        out[1*RTOT + r] = rgby;
        out[2*RTOT + r] = rgbz;
        out[3*RTOT + r] = alpha_final;
        out[4*RTOT + r] = rgbx;
        out[5*RTOT + r] = rgby;
        out[6*RTOT + r] = rgbz;
        out[7*RTOT + r] = alpha_final;
    }
}

extern "C" void kernel_launch(void* const* d_in, const int* in_sizes, int n_in,
                              void* d_out, int out_size)
{
    const float* raypos    = (const float*)d_in[0];
    const float* raydir    = (const float*)d_in[1];
    const float* tminmax   = (const float*)d_in[2];
    const float* primpos   = (const float*)d_in[3];
    const float* primrot   = (const float*)d_in[4];
    const float* primscale = (const float*)d_in[5];
    const float* tpl       = (const float*)d_in[6];
    float* out = (float*)d_out;

    convert_tpl_kernel<<<NK * VOX_PER_PRIM / 256, 256>>>(tpl);

    raymarch_kernel<<<NBLOCKS, NTHREADS>>>(
        raypos, raydir, tminmax, primpos, primrot, primscale, out);
}

// round 10
// speedup vs baseline: 1.8529x; 1.1776x over previous
#include <cuda_runtime.h>
#include <cuda_fp16.h>
#include <cstdint>

#define DT_F (1.0f/64.0f)
#define NSTEPS 64
#define NK 32
#define RTOT 16384
#define RAYS_PER_BLOCK 8
#define NTHREADS 256
#define NBLOCKS (RTOT / RAYS_PER_BLOCK)         // 2048
#define VOX_PER_PRIM 4096

// fp16-packed template: [k][z][y][x] -> uint2 (r,g | b,a as half2)
__device__ __align__(16) uint2 g_tplh[NK * VOX_PER_PRIM];

__global__ void convert_tpl_kernel(const float* __restrict__ tpl)
{
    const int idx = blockIdx.x * blockDim.x + threadIdx.x;   // 0 .. 131071
    const int k = idx >> 12;
    const int v = idx & 4095;
    const float* tk = tpl + (size_t)k * 4 * VOX_PER_PRIM;
    const float r = tk[v];
    const float g = tk[v + 4096];
    const float b = tk[v + 8192];
    const float a = tk[v + 12288];
    const half2 h0 = __floats2half2_rn(r, g);
    const half2 h1 = __floats2half2_rn(b, a);
    uint2 q;
    q.x = *reinterpret_cast<const unsigned int*>(&h0);
    q.y = *reinterpret_cast<const unsigned int*>(&h1);
    g_tplh[idx] = q;
}

__device__ __forceinline__ half2 h2_of(uint32_t u) { return *reinterpret_cast<const half2*>(&u); }

__global__ void __launch_bounds__(NTHREADS)
raymarch_kernel(const float* __restrict__ raypos,
                const float* __restrict__ raydir,
                const float* __restrict__ tminmax,
                const float* __restrict__ primpos,
                const float* __restrict__ primrot,
                const float* __restrict__ primscale,
                float* __restrict__ out)
{
    __shared__ float Mc[NK * 12];       // per-prim affine rows (m0,m1,m2,c)

    const int tid  = threadIdx.x;
    const int lane = tid & 31;
    const int w    = tid >> 5;                          // warp = local ray
    const int r    = blockIdx.x * RAYS_PER_BLOCK + w;

    // warp-uniform ray data (broadcast loads: all lanes same address)
    const float rpx = raypos[3*r+0], rpy = raypos[3*r+1], rpz = raypos[3*r+2];
    const float rdx = raydir[3*r+0], rdy = raydir[3*r+1], rdz = raydir[3*r+2];
    const float tmn = tminmax[2*r+0], tmx = tminmax[2*r+1];

    // Per-prim affine: yloc_i = M[i]·pos - c_i, M[i][j] = scale_i * rot[i][j]
    if (tid < NK) {
        const int k = tid;
        const float ppx = primpos[3*k+0], ppy = primpos[3*k+1], ppz = primpos[3*k+2];
        #pragma unroll
        for (int i = 0; i < 3; i++) {
            const float s  = primscale[3*k+i];
            const float m0 = s * primrot[9*k+3*i+0];
            const float m1 = s * primrot[9*k+3*i+1];
            const float m2 = s * primrot[9*k+3*i+2];
            Mc[12*k+4*i+0] = m0;
            Mc[12*k+4*i+1] = m1;
            Mc[12*k+4*i+2] = m2;
            Mc[12*k+4*i+3] = m0*ppx + m1*ppy + m2*ppz;
        }
    }
    __syncthreads();    // only block-wide sync in the kernel

    // Thread owns steps (lane) and (lane+32): tA, tB
    const float tA = fmaf((float)lane, DT_F, tmn);
    const float tB = fmaf((float)(lane + 32), DT_F, tmn);

    float4 acc[2];
    acc[0] = make_float4(0.f, 0.f, 0.f, 0.f);
    acc[1] = make_float4(0.f, 0.f, 0.f, 0.f);

    // warp-uniform ray t-window
    const float tray_lo = tmn;
    const float tray_hi = fmaf(63.f, DT_F, tmn);
    const float EPS = 1e-5f;

    for (int k = 0; k < NK; k++) {
        const uint2* __restrict__ tpl = g_tplh + (size_t)k * VOX_PER_PRIM;

        const float m00 = Mc[12*k+0], m01 = Mc[12*k+1], m02 = Mc[12*k+2], c0 = Mc[12*k+3];
        const float m10 = Mc[12*k+4], m11 = Mc[12*k+5], m12 = Mc[12*k+6], c1 = Mc[12*k+7];
        const float m20 = Mc[12*k+8], m21 = Mc[12*k+9], m22 = Mc[12*k+10], c2 = Mc[12*k+11];

        // ---- Warp-uniform linearization: yloc(t) = b + t*a per axis ----
        const float a0 = fmaf(m00, rdx, fmaf(m01, rdy, m02*rdz));
        const float a1 = fmaf(m10, rdx, fmaf(m11, rdy, m12*rdz));
        const float a2 = fmaf(m20, rdx, fmaf(m21, rdy, m22*rdz));
        const float b0 = fmaf(m00, rpx, fmaf(m01, rpy, fmaf(m02, rpz, -c0)));
        const float b1 = fmaf(m10, rpx, fmaf(m11, rpy, fmaf(m12, rpz, -c1)));
        const float b2 = fmaf(m20, rpx, fmaf(m21, rpy, fmaf(m22, rpz, -c2)));

        // slab cull (warp-uniform branch)
        const float i0 = 1.f / a0, i1 = 1.f / a1, i2 = 1.f / a2;
        const float u0 = (-1.f - EPS - b0) * i0, v0 = (1.f + EPS - b0) * i0;
        const float u1 = (-1.f - EPS - b1) * i1, v1 = (1.f + EPS - b1) * i1;
        const float u2 = (-1.f - EPS - b2) * i2, v2 = (1.f + EPS - b2) * i2;
        const float tlo = fmaxf(fmaxf(fminf(u0, v0), fminf(u1, v1)), fminf(u2, v2));
        const float thi = fminf(fminf(fmaxf(u0, v0), fmaxf(u1, v1)), fmaxf(u2, v2));

        if (thi < tray_lo || tlo > tray_hi || tlo > thi) continue;   // warp-uniform skip

        #pragma unroll
        for (int j = 0; j < 2; j++) {
            const float t = (j == 0) ? tA : tB;
            if (t < tlo || t > thi) continue;

            // y via the linearized form (3 FMA instead of 9)
            const float y0 = fmaf(t, a0, b0);
            const float y1 = fmaf(t, a1, b1);
            const float y2 = fmaf(t, a2, b2);

            if (fabsf(y0) <= 1.f && fabsf(y1) <= 1.f && fabsf(y2) <= 1.f) {
                const float gz = fmaf(y0, 7.5f, 7.5f);
                const float gy = fmaf(y1, 7.5f, 7.5f);
                const float gx = fmaf(y2, 7.5f, 7.5f);
                const float fz0 = fminf(floorf(gz), 14.f);
                const float fy0 = fminf(floorf(gy), 14.f);
                const float fx0 = fminf(floorf(gx), 14.f);
                const int iz = (int)fz0, iy = (int)fy0, ix = (int)fx0;
                const float fz = fminf(gz - fz0, 1.f);
                const float fy = fminf(gy - fy0, 1.f);
                const float fx = fminf(gx - fx0, 1.f);

                const int base = (iz*16 + iy)*16 + ix;
                const uint2 q000 = __ldg(tpl + base);
                const uint2 q001 = __ldg(tpl + base + 1);
                const uint2 q010 = __ldg(tpl + base + 16);
                const uint2 q011 = __ldg(tpl + base + 17);
                const uint2 q100 = __ldg(tpl + base + 256);
                const uint2 q101 = __ldg(tpl + base + 257);
                const uint2 q110 = __ldg(tpl + base + 272);
                const uint2 q111 = __ldg(tpl + base + 273);

                const float wz0 = 1.f - fz, wy0 = 1.f - fy, wx0 = 1.f - fx;
                const float w00 = wz0*wy0, w01 = wz0*fy, w10 = fz*wy0, w11 = fz*fy;

                const half2 h000 = __float2half2_rn(w00*wx0);
                const half2 h001 = __float2half2_rn(w00*fx);
                const half2 h010 = __float2half2_rn(w01*wx0);
                const half2 h011 = __float2half2_rn(w01*fx);
                const half2 h100 = __float2half2_rn(w10*wx0);
                const half2 h101 = __float2half2_rn(w10*fx);
                const half2 h110 = __float2half2_rn(w11*wx0);
                const half2 h111 = __float2half2_rn(w11*fx);

                // 8-corner trilinear in packed fp16 (rg and ba lanes)
                half2 srg = __hmul2(h000, h2_of(q000.x));
                half2 sba = __hmul2(h000, h2_of(q000.y));
                srg = __hfma2(h001, h2_of(q001.x), srg);
                sba = __hfma2(h001, h2_of(q001.y), sba);
                srg = __hfma2(h010, h2_of(q010.x), srg);
                sba = __hfma2(h010, h2_of(q010.y), sba);
                srg = __hfma2(h011, h2_of(q011.x), srg);
                sba = __hfma2(h011, h2_of(q011.y), sba);
                srg = __hfma2(h100, h2_of(q100.x), srg);
                sba = __hfma2(h100, h2_of(q100.y), sba);
                srg = __hfma2(h101, h2_of(q101.x), srg);
                sba = __hfma2(h101, h2_of(q101.y), sba);
                srg = __hfma2(h110, h2_of(q110.x), srg);
                sba = __hfma2(h110, h2_of(q110.y), sba);
                srg = __hfma2(h111, h2_of(q111.x), srg);
                sba = __hfma2(h111, h2_of(q111.y), sba);

                const float2 frg = __half22float2(srg);
                const float2 fba = __half22float2(sba);
                acc[j].x += frg.x;
                acc[j].y += frg.y;
                acc[j].z += fba.x;
                acc[j].w += fba.y;
            }
        }
    }

    // ---- Composite: alpha_i = min(prefix_i, 1); contrib_i = alpha_i - alpha_{i-1}.
    //      Steps 0..31 = lanes at j=0; steps 32..63 = lanes at j=1. ----
    const float sA = (tA < tmx) ? acc[0].w * DT_F : 0.f;
    const float sB = (tB < tmx) ? acc[1].w * DT_F : 0.f;

    float scanA = sA;
    #pragma unroll
    for (int d = 1; d < 32; d <<= 1) {
        const float v = __shfl_up_sync(0xffffffffu, scanA, d);
        if (lane >= d) scanA += v;
    }
    const float totA = __shfl_sync(0xffffffffu, scanA, 31);

    float scanB = sB;
    #pragma unroll
    for (int d = 1; d < 32; d <<= 1) {
        const float v = __shfl_up_sync(0xffffffffu, scanB, d);
        if (lane >= d) scanB += v;
    }

    const float PA = scanA;                 // inclusive prefix at step lane
    const float PB = totA + scanB;          // inclusive prefix at step lane+32

    const float contribA = fminf(PA, 1.f) - fminf(PA - sA, 1.f);
    const float contribB = fminf(PB, 1.f) - fminf(PB - sB, 1.f);

    float rgbx = acc[0].x * contribA + acc[1].x * contribB;
    float rgby = acc[0].y * contribA + acc[1].y * contribB;
    float rgbz = acc[0].z * contribA + acc[1].z * contribB;

    #pragma unroll
    for (int d = 16; d >= 1; d >>= 1) {
        rgbx += __shfl_xor_sync(0xffffffffu, rgbx, d);
        rgby += __shfl_xor_sync(0xffffffffu, rgby, d);
        rgbz += __shfl_xor_sync(0xffffffffu, rgbz, d);
    }
    const float alpha_final = fminf(totA + __shfl_sync(0xffffffffu, scanB, 31), 1.f);

    if (lane == 0) {
        // out = [rayrgb (3*R)] [rayalpha (R)] [rayrgba (4*R)]
        out[0*RTOT + r] = rgbx;
        out[1*RTOT + r] = rgby;
        out[2*RTOT + r] = rgbz;
        out[3*RTOT + r] = alpha_final;
        out[4*RTOT + r] = rgbx;
        out[5*RTOT + r] = rgby;
        out[6*RTOT + r] = rgbz;
        out[7*RTOT + r] = alpha_final;
    }
}

extern "C" void kernel_launch(void* const* d_in, const int* in_sizes, int n_in,
                              void* d_out, int out_size)
{
    const float* raypos    = (const float*)d_in[0];
    const float* raydir    = (const float*)d_in[1];
    const float* tminmax   = (const float*)d_in[2];
    const float* primpos   = (const float*)d_in[3];
    const float* primrot   = (const float*)d_in[4];
    const float* primscale = (const float*)d_in[5];
    const float* tpl       = (const float*)d_in[6];
    float* out = (float*)d_out;

    convert_tpl_kernel<<<NK * VOX_PER_PRIM / 256, 256>>>(tpl);

    raymarch_kernel<<<NBLOCKS, NTHREADS>>>(
        raypos, raydir, tminmax, primpos, primrot, primscale, out);
}